// round 12
// baseline (speedup 1.0000x reference)
#include <cuda_runtime.h>
#include <cuda_bf16.h>
#include <cstdint>

// Problem constants (B=2, T=512, C=256, HID=1024)
constexpr int Mrows = 1024;   // B*T
constexpr int Cdim  = 256;
constexpr int Hdim  = 1024;

// Static device scratch
__device__ __nv_bfloat16 g_hid[Mrows * Hdim];
__device__ __nv_bfloat16 g_W2 [Cdim * Hdim];

// ---------------------------------------------------------------------------
// PTX helpers
// ---------------------------------------------------------------------------
__device__ __forceinline__ uint32_t smem_u32(const void* p) {
    return (uint32_t)__cvta_generic_to_shared(p);
}
__device__ __forceinline__ void ldsm_x4(uint32_t& r0, uint32_t& r1,
                                        uint32_t& r2, uint32_t& r3, uint32_t a) {
    asm volatile("ldmatrix.sync.aligned.m8n8.x4.shared.b16 {%0,%1,%2,%3},[%4];"
                 : "=r"(r0), "=r"(r1), "=r"(r2), "=r"(r3) : "r"(a));
}
__device__ __forceinline__ void ldsm_x2(uint32_t& r0, uint32_t& r1, uint32_t a) {
    asm volatile("ldmatrix.sync.aligned.m8n8.x2.shared.b16 {%0,%1},[%2];"
                 : "=r"(r0), "=r"(r1) : "r"(a));
}
__device__ __forceinline__ void mma_bf16(float* c, const uint32_t* a, const uint32_t* b) {
    asm volatile(
        "mma.sync.aligned.m16n8k16.row.col.f32.bf16.bf16.f32 "
        "{%0,%1,%2,%3},{%4,%5,%6,%7},{%8,%9},{%0,%1,%2,%3};"
        : "+f"(c[0]), "+f"(c[1]), "+f"(c[2]), "+f"(c[3])
        : "r"(a[0]), "r"(a[1]), "r"(a[2]), "r"(a[3]), "r"(b[0]), "r"(b[1]));
}
__device__ __forceinline__ void cp_async16(uint32_t s, const void* g) {
    asm volatile("cp.async.cg.shared.global [%0], [%1], 16;" :: "r"(s), "l"(g));
}
__device__ __forceinline__ void cp_commit() { asm volatile("cp.async.commit_group;"); }
template <int N> __device__ __forceinline__ void cp_wait() {
    asm volatile("cp.async.wait_group %0;" :: "n"(N));
}
// Convert 8 consecutive fp32 -> 8 bf16 (one uint4 store)
__device__ __forceinline__ void cvt8(const float* __restrict__ s,
                                     __nv_bfloat16* __restrict__ d) {
    const float4 v0 = *reinterpret_cast<const float4*>(s);
    const float4 v1 = *reinterpret_cast<const float4*>(s + 4);
    __nv_bfloat162 h[4];
    h[0].x = __float2bfloat16(v0.x); h[0].y = __float2bfloat16(v0.y);
    h[1].x = __float2bfloat16(v0.z); h[1].y = __float2bfloat16(v0.w);
    h[2].x = __float2bfloat16(v1.x); h[2].y = __float2bfloat16(v1.y);
    h[3].x = __float2bfloat16(v1.z); h[3].y = __float2bfloat16(v1.w);
    *reinterpret_cast<uint4*>(d) = *reinterpret_cast<uint4*>(h);
}

// ===========================================================================
// Kernel 1: GEMM1' = inline LN + fp32-W1 reg-prefetch pipeline + HMMA + relu
//   hid = relu( LN(x+bp) @ W1^T + bf1 )    M=1024 N=1024 K=256
// grid (8 n, 16 m) = 128 blocks, 256 threads.
//   A (64 x 256 bf16, stride 264) : built once by inline LN, resident.
//   B (W1): 4 stages of BK=64; stage s+1 prefetched into regs via LDG.128
//           during stage-s MMAs, then cvt->STS bf16 after the stage barrier.
// Side job: convert this block's W2 slice fp32->bf16 (consumed by kernel 2).
// ===========================================================================
constexpr int LDA1 = 264;              // A row stride (bf16): 528B, 16B phase
constexpr int LDB1 = 72;               // B tile row stride (bf16)
constexpr int SMEM1 = 64 * LDA1 * 2 + 2 * 128 * LDB1 * 2;   // 70656 B

__global__ void __launch_bounds__(256, 1)
gemm1_fused(const float* __restrict__ x,
            const float* __restrict__ bp,
            const float* __restrict__ g2,
            const float* __restrict__ b2,
            const float* __restrict__ W1,
            const float* __restrict__ bf1,
            const float* __restrict__ W2)
{
    extern __shared__ char smem[];
    __nv_bfloat16* As = reinterpret_cast<__nv_bfloat16*>(smem);              // 64*264
    __nv_bfloat16* Bs = As + 64 * LDA1;                                      // 2*128*72

    const int tid  = threadIdx.x;
    const int lane = tid & 31;
    const int warp = tid >> 5;
    const int m0   = blockIdx.y * 64;
    const int n0   = blockIdx.x * 128;

    // --- B stage-0 prefetch: thread t -> W1 row n0 + (t>>1), cols (t&1)*32..+32
    const int brow = tid >> 1;
    const int bcol = (tid & 1) * 32;
    float breg[8][4];
    {
        const float* src = W1 + (size_t)(n0 + brow) * Cdim + 0 * 64 + bcol;
        #pragma unroll
        for (int j = 0; j < 8; j++)
            *reinterpret_cast<float4*>(breg[j]) =
                *reinterpret_cast<const float4*>(src + j * 4);
    }

    // --- W2 side job (consumed only by kernel 2)
    {
        const int base = ((int)blockIdx.y * 8 + (int)blockIdx.x) * 2048 + tid * 8;
        cvt8(W2 + base, g_W2 + base);
    }

    // --- Inline LN: warp w -> rows w*8 .. w*8+7, lane covers 8 cols
    {
        const int c0 = lane * 8;
        const float4 pa = *reinterpret_cast<const float4*>(bp + c0);
        const float4 pb = *reinterpret_cast<const float4*>(bp + c0 + 4);
        const float4 ga = *reinterpret_cast<const float4*>(g2 + c0);
        const float4 gb = *reinterpret_cast<const float4*>(g2 + c0 + 4);
        const float4 ba = *reinterpret_cast<const float4*>(b2 + c0);
        const float4 bb = *reinterpret_cast<const float4*>(b2 + c0 + 4);
        const float gg[8]  = {ga.x, ga.y, ga.z, ga.w, gb.x, gb.y, gb.z, gb.w};
        const float bbv[8] = {ba.x, ba.y, ba.z, ba.w, bb.x, bb.y, bb.z, bb.w};
        const float pp[8]  = {pa.x, pa.y, pa.z, pa.w, pb.x, pb.y, pb.z, pb.w};
        #pragma unroll
        for (int rr = 0; rr < 8; rr++) {
            const int row = warp * 8 + rr;
            const float* rp = x + (size_t)(m0 + row) * Cdim + c0;
            const float4 a = *reinterpret_cast<const float4*>(rp);
            const float4 b = *reinterpret_cast<const float4*>(rp + 4);
            float v[8] = {a.x + pp[0], a.y + pp[1], a.z + pp[2], a.w + pp[3],
                          b.x + pp[4], b.y + pp[5], b.z + pp[6], b.w + pp[7]};
            float s = 0.f, q = 0.f;
            #pragma unroll
            for (int j = 0; j < 8; j++) { s += v[j]; q += v[j] * v[j]; }
            #pragma unroll
            for (int o = 16; o > 0; o >>= 1) {
                s += __shfl_xor_sync(0xffffffffu, s, o);
                q += __shfl_xor_sync(0xffffffffu, q, o);
            }
            const float mean = s * (1.0f / Cdim);
            const float var  = q * (1.0f / Cdim) - mean * mean;
            const float inv  = rsqrtf(var + 1e-5f);
            __nv_bfloat162 h[4];
            #pragma unroll
            for (int j = 0; j < 4; j++) {
                h[j].x = __float2bfloat16((v[2*j]   - mean) * inv * gg[2*j]   + bbv[2*j]);
                h[j].y = __float2bfloat16((v[2*j+1] - mean) * inv * gg[2*j+1] + bbv[2*j+1]);
            }
            *reinterpret_cast<uint4*>(&As[row * LDA1 + c0]) =
                *reinterpret_cast<uint4*>(h);
        }
    }

    // --- Commit stage 0 B to smem
    {
        __nv_bfloat16* dst = Bs + brow * LDB1 + bcol;
        #pragma unroll
        for (int j = 0; j < 4; j++) {
            __nv_bfloat162 h[4];
            h[0].x = __float2bfloat16(breg[2*j][0]);   h[0].y = __float2bfloat16(breg[2*j][1]);
            h[1].x = __float2bfloat16(breg[2*j][2]);   h[1].y = __float2bfloat16(breg[2*j][3]);
            h[2].x = __float2bfloat16(breg[2*j+1][0]); h[2].y = __float2bfloat16(breg[2*j+1][1]);
            h[3].x = __float2bfloat16(breg[2*j+1][2]); h[3].y = __float2bfloat16(breg[2*j+1][3]);
            *reinterpret_cast<uint4*>(dst + j * 8) = *reinterpret_cast<uint4*>(h);
        }
    }
    __syncthreads();   // As + Bs[0] visible

    // --- Warp tiling: 2x4 warps, WM=32 WN=32 -> MT=2, NTt=4 (8 acc chains)
    const int wm = warp >> 2;
    const int wn = warp & 3;
    float acc[2][4][4];
    #pragma unroll
    for (int i = 0; i < 2; i++)
        #pragma unroll
        for (int j = 0; j < 4; j++)
            #pragma unroll
            for (int r = 0; r < 4; r++) acc[i][j][r] = 0.f;

    #pragma unroll
    for (int s = 0; s < 4; s++) {
        // Prefetch next stage's W1 into regs (latency hidden under MMAs below)
        if (s + 1 < 4) {
            const float* src = W1 + (size_t)(n0 + brow) * Cdim + (s + 1) * 64 + bcol;
            #pragma unroll
            for (int j = 0; j < 8; j++)
                *reinterpret_cast<float4*>(breg[j]) =
                    *reinterpret_cast<const float4*>(src + j * 4);
        }

        const __nv_bfloat16* Bb = Bs + (s & 1) * 128 * LDB1;
        #pragma unroll
        for (int k16 = 0; k16 < 64; k16 += 16) {
            const int ksA = s * 64 + k16;     // col in resident A
            uint32_t afrag[2][4];
            #pragma unroll
            for (int mt = 0; mt < 2; mt++) {
                const int row = wm * 32 + mt * 16 + (lane & 15);
                const int col = ksA + (lane >> 4) * 8;
                ldsm_x4(afrag[mt][0], afrag[mt][1], afrag[mt][2], afrag[mt][3],
                        smem_u32(&As[row * LDA1 + col]));
            }
            uint32_t bfrag[4][2];
            #pragma unroll
            for (int nt = 0; nt < 4; nt++) {
                const int row = wn * 32 + nt * 8 + (lane & 7);
                const int col = k16 + ((lane >> 3) & 1) * 8;
                ldsm_x2(bfrag[nt][0], bfrag[nt][1],
                        smem_u32(&Bb[row * LDB1 + col]));
            }
            #pragma unroll
            for (int mt = 0; mt < 2; mt++)
                #pragma unroll
                for (int nt = 0; nt < 4; nt++)
                    mma_bf16(acc[mt][nt], afrag[mt], bfrag[nt]);
        }
        __syncthreads();   // all warps done with buffer (s+1)&1 from stage s-1

        if (s + 1 < 4) {
            __nv_bfloat16* dst = Bs + ((s + 1) & 1) * 128 * LDB1 + brow * LDB1 + bcol;
            #pragma unroll
            for (int j = 0; j < 4; j++) {
                __nv_bfloat162 h[4];
                h[0].x = __float2bfloat16(breg[2*j][0]);   h[0].y = __float2bfloat16(breg[2*j][1]);
                h[1].x = __float2bfloat16(breg[2*j][2]);   h[1].y = __float2bfloat16(breg[2*j][3]);
                h[2].x = __float2bfloat16(breg[2*j+1][0]); h[2].y = __float2bfloat16(breg[2*j+1][1]);
                h[3].x = __float2bfloat16(breg[2*j+1][2]); h[3].y = __float2bfloat16(breg[2*j+1][3]);
                *reinterpret_cast<uint4*>(dst + j * 8) = *reinterpret_cast<uint4*>(h);
            }
            __syncthreads();
        }
    }

    // --- Epilogue: relu(acc + bf1) -> bf16 g_hid
    #pragma unroll
    for (int mt = 0; mt < 2; mt++) {
        #pragma unroll
        for (int nt = 0; nt < 4; nt++) {
            const int m = m0 + wm * 32 + mt * 16 + (lane >> 2);
            const int n = n0 + wn * 32 + nt * 8 + (lane & 3) * 2;
            const float b0 = bf1[n], b1 = bf1[n + 1];
            __nv_bfloat162 p;
            p.x = __float2bfloat16(fmaxf(acc[mt][nt][0] + b0, 0.f));
            p.y = __float2bfloat16(fmaxf(acc[mt][nt][1] + b1, 0.f));
            *reinterpret_cast<__nv_bfloat162*>(&g_hid[(size_t)m * Hdim + n]) = p;
            p.x = __float2bfloat16(fmaxf(acc[mt][nt][2] + b0, 0.f));
            p.y = __float2bfloat16(fmaxf(acc[mt][nt][3] + b1, 0.f));
            *reinterpret_cast<__nv_bfloat162*>(&g_hid[(size_t)(m + 8) * Hdim + n]) = p;
        }
    }
}

// ===========================================================================
// Kernel 2: GEMM2 (proven R4 config, unchanged)
//   out = hid @ W2^T + x + bp + bf2     M=1024 N=256 K=1024
// grid 8x16 = 128 blocks, 256 thr, BM=64 BN=32 BK=128 double-buffered.
// ===========================================================================
__global__ void __launch_bounds__(256, 1)
gemm2_kernel(const __nv_bfloat16* __restrict__ A,
             const __nv_bfloat16* __restrict__ B,
             const float* __restrict__ x,
             const float* __restrict__ bp,
             const float* __restrict__ bf2,
             float* __restrict__ out)
{
    constexpr int BM = 64, BN = 32, BK = 128;
    constexpr int LDS = BK + 8;     // 136
    constexpr int NT  = 256;
    __shared__ __nv_bfloat16 As[2][BM * LDS];
    __shared__ __nv_bfloat16 Bs[2][BN * LDS];

    const int tid  = threadIdx.x;
    const int lane = tid & 31;
    const int warp = tid >> 5;
    const int wm   = warp >> 1;      // 4x2 warps: WM=16, WN=16
    const int wn   = warp & 1;
    const int m0   = blockIdx.y * BM;
    const int n0   = blockIdx.x * BN;
    constexpr int kIters = Hdim / BK;   // 8

    auto load_stage = [&](int buf, int k0) {
        #pragma unroll
        for (int i = tid; i < BM * BK / 8; i += NT) {
            const int r = i / (BK / 8), cv = i % (BK / 8);
            cp_async16(smem_u32(&As[buf][r * LDS + cv * 8]),
                       &A[(size_t)(m0 + r) * Hdim + k0 + cv * 8]);
        }
        #pragma unroll
        for (int i = tid; i < BN * BK / 8; i += NT) {
            const int r = i / (BK / 8), cv = i % (BK / 8);
            cp_async16(smem_u32(&Bs[buf][r * LDS + cv * 8]),
                       &B[(size_t)(n0 + r) * Hdim + k0 + cv * 8]);
        }
        cp_commit();
    };

    float acc[2][4] = {};
    load_stage(0, 0);

    for (int it = 0; it < kIters; it++) {
        const int buf = it & 1;
        if (it + 1 < kIters) { load_stage((it + 1) & 1, (it + 1) * BK); cp_wait<1>(); }
        else                 { cp_wait<0>(); }
        __syncthreads();

        #pragma unroll
        for (int ks = 0; ks < BK; ks += 16) {
            uint32_t afrag[4];
            {
                const int row = wm * 16 + (lane & 15);
                const int col = ks + (lane >> 4) * 8;
                ldsm_x4(afrag[0], afrag[1], afrag[2], afrag[3],
                        smem_u32(&As[buf][row * LDS + col]));
            }
            uint32_t bfrag[2][2];
            #pragma unroll
            for (int nt = 0; nt < 2; nt++) {
                const int row = wn * 16 + nt * 8 + (lane & 7);
                const int col = ks + ((lane >> 3) & 1) * 8;
                ldsm_x2(bfrag[nt][0], bfrag[nt][1],
                        smem_u32(&Bs[buf][row * LDS + col]));
            }
            #pragma unroll
            for (int nt = 0; nt < 2; nt++)
                mma_bf16(acc[nt], afrag, bfrag[nt]);
        }
        __syncthreads();
    }

    // Epilogue: acc + x + bp + bf2 -> fp32
    #pragma unroll
    for (int nt = 0; nt < 2; nt++) {
        const int m = m0 + wm * 16 + (lane >> 2);
        const int n = n0 + wn * 16 + nt * 8 + (lane & 3) * 2;
        const float b0 = bp[n] + bf2[n];
        const float b1 = bp[n + 1] + bf2[n + 1];
        const float2 r0 = *reinterpret_cast<const float2*>(&x[(size_t)m * Cdim + n]);
        const float2 r1 = *reinterpret_cast<const float2*>(&x[(size_t)(m + 8) * Cdim + n]);
        float2 p;
        p.x = acc[nt][0] + r0.x + b0; p.y = acc[nt][1] + r0.y + b1;
        *reinterpret_cast<float2*>(&out[(size_t)m * Cdim + n]) = p;
        p.x = acc[nt][2] + r1.x + b0; p.y = acc[nt][3] + r1.y + b1;
        *reinterpret_cast<float2*>(&out[(size_t)(m + 8) * Cdim + n]) = p;
    }
}

// ---------------------------------------------------------------------------
// Attention branch is exactly 0 (transform *= 0.0)  =>  sa == bp.
//   y = (x + bp) + relu(LN(x+bp)@W1^T + bf1) @ W2^T + bf2
// Inputs: 0:x 1:Wt 2:Wp 3:bp 4:g1 5:b1 6:g2 7:b2 8:W1 9:bf1 10:W2 11:bf2
// ---------------------------------------------------------------------------
extern "C" void kernel_launch(void* const* d_in, const int* in_sizes, int n_in,
                              void* d_out, int out_size)
{
    const float* x   = (const float*)d_in[0];
    const float* bp  = (const float*)d_in[3];
    const float* g2  = (const float*)d_in[6];
    const float* b2  = (const float*)d_in[7];
    const float* W1  = (const float*)d_in[8];
    const float* bf1 = (const float*)d_in[9];
    const float* W2  = (const float*)d_in[10];
    const float* bf2 = (const float*)d_in[11];
    float* out = (float*)d_out;

    __nv_bfloat16 *hidp, *w2p;
    cudaGetSymbolAddress((void**)&hidp, g_hid);
    cudaGetSymbolAddress((void**)&w2p,  g_W2);

    cudaFuncSetAttribute(gemm1_fused,
                         cudaFuncAttributeMaxDynamicSharedMemorySize, SMEM1);

    // 1) hid = relu(LN(x+bp) @ W1^T + bf1)  — LN + W1/W2 convert fused in
    gemm1_fused<<<dim3(Hdim / 128, Mrows / 64), 256, SMEM1>>>(
        x, bp, g2, b2, W1, bf1, W2);

    // 2) out = hid @ W2^T + x + bp + bf2
    gemm2_kernel<<<dim3(Cdim / 32, Mrows / 64), 256>>>(
        hidp, w2p, x, bp, bf2, out);
}

// round 13
// speedup vs baseline: 1.0484x; 1.0484x over previous
#include <cuda_runtime.h>
#include <cuda_bf16.h>
#include <cstdint>

// Problem constants (B=2, T=512, C=256, HID=1024)
constexpr int Mrows = 1024;   // B*T
constexpr int Cdim  = 256;
constexpr int Hdim  = 1024;

// Static device scratch
__device__ __nv_bfloat16 g_h2 [Mrows * Cdim];
__device__ __nv_bfloat16 g_hid[Mrows * Hdim];
__device__ __nv_bfloat16 g_W1 [Hdim * Cdim];
__device__ __nv_bfloat16 g_W2 [Cdim * Hdim];

// ---------------------------------------------------------------------------
// PTX helpers
// ---------------------------------------------------------------------------
__device__ __forceinline__ uint32_t smem_u32(const void* p) {
    return (uint32_t)__cvta_generic_to_shared(p);
}
__device__ __forceinline__ void ldsm_x4(uint32_t& r0, uint32_t& r1,
                                        uint32_t& r2, uint32_t& r3, uint32_t a) {
    asm volatile("ldmatrix.sync.aligned.m8n8.x4.shared.b16 {%0,%1,%2,%3},[%4];"
                 : "=r"(r0), "=r"(r1), "=r"(r2), "=r"(r3) : "r"(a));
}
__device__ __forceinline__ void ldsm_x2(uint32_t& r0, uint32_t& r1, uint32_t a) {
    asm volatile("ldmatrix.sync.aligned.m8n8.x2.shared.b16 {%0,%1},[%2];"
                 : "=r"(r0), "=r"(r1) : "r"(a));
}
__device__ __forceinline__ void mma_bf16(float* c, const uint32_t* a, const uint32_t* b) {
    asm volatile(
        "mma.sync.aligned.m16n8k16.row.col.f32.bf16.bf16.f32 "
        "{%0,%1,%2,%3},{%4,%5,%6,%7},{%8,%9},{%0,%1,%2,%3};"
        : "+f"(c[0]), "+f"(c[1]), "+f"(c[2]), "+f"(c[3])
        : "r"(a[0]), "r"(a[1]), "r"(a[2]), "r"(a[3]), "r"(b[0]), "r"(b[1]));
}
__device__ __forceinline__ void cp_async16(uint32_t s, const void* g) {
    asm volatile("cp.async.cg.shared.global [%0], [%1], 16;" :: "r"(s), "l"(g));
}
__device__ __forceinline__ void cp_commit() { asm volatile("cp.async.commit_group;"); }
template <int N> __device__ __forceinline__ void cp_wait() {
    asm volatile("cp.async.wait_group %0;" :: "n"(N));
}

// ---------------------------------------------------------------------------
// Fused prep kernel (proven R4 config):
//   blocks [0, 512)   : convert W1,W2 fp32 -> bf16 (4 floats per thread)
//   blocks [512, 640) : LN, 8 rows per block (one warp per row)
// ---------------------------------------------------------------------------
__global__ void prep_kernel(const float* __restrict__ W1,
                            const float* __restrict__ W2,
                            const float* __restrict__ x,
                            const float* __restrict__ bp,
                            const float* __restrict__ g2,
                            const float* __restrict__ b2)
{
    if (blockIdx.x < 512) {
        const int i   = blockIdx.x * blockDim.x + threadIdx.x;
        const int idx = i * 4;
        const float* s;
        __nv_bfloat16* d;
        if (idx < Hdim * Cdim) { s = W1 + idx;                 d = g_W1 + idx; }
        else                   { s = W2 + (idx - Hdim * Cdim); d = g_W2 + (idx - Hdim * Cdim); }
        const float4 v = *reinterpret_cast<const float4*>(s);
        __nv_bfloat162 p0, p1;
        p0.x = __float2bfloat16(v.x); p0.y = __float2bfloat16(v.y);
        p1.x = __float2bfloat16(v.z); p1.y = __float2bfloat16(v.w);
        reinterpret_cast<__nv_bfloat162*>(d)[0] = p0;
        reinterpret_cast<__nv_bfloat162*>(d)[1] = p1;
        return;
    }
    // LN part: one warp per row
    const int gtid = (blockIdx.x - 512) * blockDim.x + threadIdx.x;
    const int row  = gtid >> 5;
    const int lane = gtid & 31;
    const int c0   = lane * 8;
    const float* rp = x + (size_t)row * Cdim + c0;

    float v[8];
    {
        const float4 a  = *reinterpret_cast<const float4*>(rp);
        const float4 b  = *reinterpret_cast<const float4*>(rp + 4);
        const float4 pa = *reinterpret_cast<const float4*>(bp + c0);
        const float4 pb = *reinterpret_cast<const float4*>(bp + c0 + 4);
        v[0] = a.x + pa.x; v[1] = a.y + pa.y; v[2] = a.z + pa.z; v[3] = a.w + pa.w;
        v[4] = b.x + pb.x; v[5] = b.y + pb.y; v[6] = b.z + pb.z; v[7] = b.w + pb.w;
    }
    float s = 0.f, q = 0.f;
    #pragma unroll
    for (int j = 0; j < 8; j++) { s += v[j]; q += v[j] * v[j]; }
    #pragma unroll
    for (int o = 16; o > 0; o >>= 1) {
        s += __shfl_xor_sync(0xffffffffu, s, o);
        q += __shfl_xor_sync(0xffffffffu, q, o);
    }
    const float mean = s * (1.0f / Cdim);
    const float var  = q * (1.0f / Cdim) - mean * mean;
    const float inv  = rsqrtf(var + 1e-5f);

    const float4 ga = *reinterpret_cast<const float4*>(g2 + c0);
    const float4 gb = *reinterpret_cast<const float4*>(g2 + c0 + 4);
    const float4 ba = *reinterpret_cast<const float4*>(b2 + c0);
    const float4 bb = *reinterpret_cast<const float4*>(b2 + c0 + 4);
    const float gg[8]  = {ga.x, ga.y, ga.z, ga.w, gb.x, gb.y, gb.z, gb.w};
    const float bbv[8] = {ba.x, ba.y, ba.z, ba.w, bb.x, bb.y, bb.z, bb.w};

    __nv_bfloat162 o[4];
    #pragma unroll
    for (int j = 0; j < 4; j++) {
        o[j].x = __float2bfloat16((v[2*j]   - mean) * inv * gg[2*j]   + bbv[2*j]);
        o[j].y = __float2bfloat16((v[2*j+1] - mean) * inv * gg[2*j+1] + bbv[2*j+1]);
    }
    *reinterpret_cast<uint4*>(&g_h2[(size_t)row * Cdim + c0]) =
        *reinterpret_cast<uint4*>(o);
}

// ---------------------------------------------------------------------------
// Double-buffered cp.async bf16 HMMA GEMM (R4 inner loops, smaller tiles ->
// 2 CTAs per SM so barriers only stall half the SM).
//   C[m,n] = sum_k A[m,k]*B[n,k]   (A:[M,K], B:[N,K] bf16 row-major)
// MODE 0: relu(acc + bias[n]) -> bf16 Cout
// MODE 1: acc + resid[m,n] + bias[n] + bias2[n] -> fp32 Cout
// ---------------------------------------------------------------------------
template <int BM, int BN, int BK, int WM, int WN, int MODE>
__global__ void __launch_bounds__((BM / WM) * (BN / WN) * 32, 2)
mma_gemm(const __nv_bfloat16* __restrict__ A,
         const __nv_bfloat16* __restrict__ B,
         void* __restrict__ Cout,
         int Ktot, int Ntot,
         const float* __restrict__ bias,
         const float* __restrict__ resid,
         const float* __restrict__ bias2)
{
    constexpr int WARPS_M = BM / WM;
    constexpr int WARPS_N = BN / WN;
    constexpr int NT  = WARPS_M * WARPS_N * 32;
    constexpr int LDS = BK + 8;
    constexpr int MT  = WM / 16;
    constexpr int NTt = WN / 8;

    __shared__ __nv_bfloat16 As[2][BM * LDS];
    __shared__ __nv_bfloat16 Bs[2][BN * LDS];

    const int tid  = threadIdx.x;
    const int lane = tid & 31;
    const int warp = tid >> 5;
    const int wm   = warp / WARPS_N;
    const int wn   = warp % WARPS_N;
    const int m0   = blockIdx.y * BM;
    const int n0   = blockIdx.x * BN;
    const int kIters = Ktot / BK;

    auto load_stage = [&](int buf, int k0) {
        #pragma unroll
        for (int i = tid; i < BM * BK / 8; i += NT) {
            const int r = i / (BK / 8), cv = i % (BK / 8);
            cp_async16(smem_u32(&As[buf][r * LDS + cv * 8]),
                       &A[(size_t)(m0 + r) * Ktot + k0 + cv * 8]);
        }
        #pragma unroll
        for (int i = tid; i < BN * BK / 8; i += NT) {
            const int r = i / (BK / 8), cv = i % (BK / 8);
            cp_async16(smem_u32(&Bs[buf][r * LDS + cv * 8]),
                       &B[(size_t)(n0 + r) * Ktot + k0 + cv * 8]);
        }
        cp_commit();
    };

    float acc[MT][NTt][4];
    #pragma unroll
    for (int i = 0; i < MT; i++)
        #pragma unroll
        for (int j = 0; j < NTt; j++)
            #pragma unroll
            for (int r = 0; r < 4; r++) acc[i][j][r] = 0.f;

    load_stage(0, 0);

    for (int it = 0; it < kIters; it++) {
        const int buf = it & 1;
        if (it + 1 < kIters) {
            load_stage((it + 1) & 1, (it + 1) * BK);
            cp_wait<1>();
        } else {
            cp_wait<0>();
        }
        __syncthreads();

        #pragma unroll
        for (int ks = 0; ks < BK; ks += 16) {
            uint32_t afrag[MT][4];
            #pragma unroll
            for (int mt = 0; mt < MT; mt++) {
                const int row = wm * WM + mt * 16 + (lane & 15);
                const int col = ks + (lane >> 4) * 8;
                ldsm_x4(afrag[mt][0], afrag[mt][1], afrag[mt][2], afrag[mt][3],
                        smem_u32(&As[buf][row * LDS + col]));
            }
            uint32_t bfrag[NTt][2];
            #pragma unroll
            for (int nt = 0; nt < NTt; nt++) {
                const int row = wn * WN + nt * 8 + (lane & 7);
                const int col = ks + ((lane >> 3) & 1) * 8;
                ldsm_x2(bfrag[nt][0], bfrag[nt][1],
                        smem_u32(&Bs[buf][row * LDS + col]));
            }
            #pragma unroll
            for (int mt = 0; mt < MT; mt++)
                #pragma unroll
                for (int nt = 0; nt < NTt; nt++)
                    mma_bf16(acc[mt][nt], afrag[mt], bfrag[nt]);
        }
        __syncthreads();
    }

    // Epilogue
    #pragma unroll
    for (int mt = 0; mt < MT; mt++) {
        #pragma unroll
        for (int nt = 0; nt < NTt; nt++) {
            const int m = m0 + wm * WM + mt * 16 + (lane >> 2);
            const int n = n0 + wn * WN + nt * 8 + (lane & 3) * 2;
            float c0 = acc[mt][nt][0], c1 = acc[mt][nt][1];
            float c2 = acc[mt][nt][2], c3 = acc[mt][nt][3];
            if (MODE == 0) {
                const float b0 = bias[n], b1 = bias[n + 1];
                c0 = fmaxf(c0 + b0, 0.f); c1 = fmaxf(c1 + b1, 0.f);
                c2 = fmaxf(c2 + b0, 0.f); c3 = fmaxf(c3 + b1, 0.f);
                __nv_bfloat16* O = (__nv_bfloat16*)Cout;
                __nv_bfloat162 p;
                p.x = __float2bfloat16(c0); p.y = __float2bfloat16(c1);
                *reinterpret_cast<__nv_bfloat162*>(&O[(size_t)m * Ntot + n]) = p;
                p.x = __float2bfloat16(c2); p.y = __float2bfloat16(c3);
                *reinterpret_cast<__nv_bfloat162*>(&O[(size_t)(m + 8) * Ntot + n]) = p;
            } else {
                float* O = (float*)Cout;
                const float b0 = bias[n] + bias2[n];
                const float b1 = bias[n + 1] + bias2[n + 1];
                const float2 r0 = *reinterpret_cast<const float2*>(&resid[(size_t)m * Ntot + n]);
                const float2 r1 = *reinterpret_cast<const float2*>(&resid[(size_t)(m + 8) * Ntot + n]);
                float2 p;
                p.x = c0 + r0.x + b0; p.y = c1 + r0.y + b1;
                *reinterpret_cast<float2*>(&O[(size_t)m * Ntot + n]) = p;
                p.x = c2 + r1.x + b0; p.y = c3 + r1.y + b1;
                *reinterpret_cast<float2*>(&O[(size_t)(m + 8) * Ntot + n]) = p;
            }
        }
    }
}

// ---------------------------------------------------------------------------
// Attention branch is exactly 0 (transform *= 0.0)  =>  sa == bp.
//   y = (x + bp) + relu(LN(x+bp)@W1^T + bf1) @ W2^T + bf2
// Inputs: 0:x 1:Wt 2:Wp 3:bp 4:g1 5:b1 6:g2 7:b2 8:W1 9:bf1 10:W2 11:bf2
// ---------------------------------------------------------------------------
extern "C" void kernel_launch(void* const* d_in, const int* in_sizes, int n_in,
                              void* d_out, int out_size)
{
    const float* x   = (const float*)d_in[0];
    const float* bp  = (const float*)d_in[3];
    const float* g2  = (const float*)d_in[6];
    const float* b2  = (const float*)d_in[7];
    const float* W1  = (const float*)d_in[8];
    const float* bf1 = (const float*)d_in[9];
    const float* W2  = (const float*)d_in[10];
    const float* bf2 = (const float*)d_in[11];
    float* out = (float*)d_out;

    __nv_bfloat16 *h2p, *hidp, *w1p, *w2p;
    cudaGetSymbolAddress((void**)&h2p,  g_h2);
    cudaGetSymbolAddress((void**)&hidp, g_hid);
    cudaGetSymbolAddress((void**)&w1p,  g_W1);
    cudaGetSymbolAddress((void**)&w2p,  g_W2);

    // 1) fused: convert W1,W2 -> bf16  +  LN -> bf16 h2
    prep_kernel<<<512 + 128, 256>>>(W1, W2, x, bp, g2, b2);

    // 2) hid = relu(h2 @ W1^T + bf1) : M=1024 N=1024 K=256 -> bf16
    //    64x64 tiles, 256 thr (2x4 warps, WM=32 WN=16), grid 16x16 = 256
    //    blocks -> 2 CTAs/SM (smem 36864 B each)
    mma_gemm<64, 64, 64, 32, 16, 0>
        <<<dim3(Hdim / 64, Mrows / 64), 256>>>(
            h2p, w1p, hidp, Cdim, Hdim, bf1, nullptr, nullptr);

    // 3) out = hid @ W2^T + x + bp + bf2 : M=1024 N=256 K=1024 -> fp32
    //    32x32 tiles, 128 thr (2x2 warps, WM=16 WN=16), grid 8x32 = 256
    //    blocks -> 2 CTAs/SM (smem 34816 B each)
    mma_gemm<32, 32, 128, 16, 16, 1>
        <<<dim3(Cdim / 32, Mrows / 32), 128>>>(
            hidp, w2p, out, Hdim, Cdim, bp, x, bf2);
}

// round 14
// speedup vs baseline: 1.0626x; 1.0135x over previous
#include <cuda_runtime.h>
#include <cuda_bf16.h>
#include <cstdint>

// Problem constants (B=2, T=512, C=256, HID=1024)
constexpr int Mrows = 1024;   // B*T
constexpr int Cdim  = 256;
constexpr int Hdim  = 1024;
constexpr int NBLK  = 128;    // persistent grid, all co-resident
constexpr int NTHR  = 256;

// Static device scratch
__device__ __nv_bfloat16 g_h2 [Mrows * Cdim];
__device__ __nv_bfloat16 g_hid[Mrows * Hdim];
__device__ __nv_bfloat16 g_W1 [Hdim * Cdim];
__device__ __nv_bfloat16 g_W2 [Cdim * Hdim];
__device__ unsigned      g_bar;        // monotonic ticket barrier
__device__ int           g_flag[NBLK]; // hid-tile ready flags (reset each launch)

// ---------------------------------------------------------------------------
// PTX helpers
// ---------------------------------------------------------------------------
__device__ __forceinline__ uint32_t smem_u32(const void* p) {
    return (uint32_t)__cvta_generic_to_shared(p);
}
__device__ __forceinline__ void ldsm_x4(uint32_t& r0, uint32_t& r1,
                                        uint32_t& r2, uint32_t& r3, uint32_t a) {
    asm volatile("ldmatrix.sync.aligned.m8n8.x4.shared.b16 {%0,%1,%2,%3},[%4];"
                 : "=r"(r0), "=r"(r1), "=r"(r2), "=r"(r3) : "r"(a));
}
__device__ __forceinline__ void ldsm_x2(uint32_t& r0, uint32_t& r1, uint32_t a) {
    asm volatile("ldmatrix.sync.aligned.m8n8.x2.shared.b16 {%0,%1},[%2];"
                 : "=r"(r0), "=r"(r1) : "r"(a));
}
__device__ __forceinline__ void mma_bf16(float* c, const uint32_t* a, const uint32_t* b) {
    asm volatile(
        "mma.sync.aligned.m16n8k16.row.col.f32.bf16.bf16.f32 "
        "{%0,%1,%2,%3},{%4,%5,%6,%7},{%8,%9},{%0,%1,%2,%3};"
        : "+f"(c[0]), "+f"(c[1]), "+f"(c[2]), "+f"(c[3])
        : "r"(a[0]), "r"(a[1]), "r"(a[2]), "r"(a[3]), "r"(b[0]), "r"(b[1]));
}
__device__ __forceinline__ void cp_async16(uint32_t s, const void* g) {
    asm volatile("cp.async.cg.shared.global [%0], [%1], 16;" :: "r"(s), "l"(g));
}
__device__ __forceinline__ void cp_commit() { asm volatile("cp.async.commit_group;"); }
template <int N> __device__ __forceinline__ void cp_wait() {
    asm volatile("cp.async.wait_group %0;" :: "n"(N));
}
// Convert 8 consecutive fp32 -> 8 bf16 (one uint4 store)
__device__ __forceinline__ void cvt8(const float* __restrict__ s,
                                     __nv_bfloat16* __restrict__ d) {
    const float4 v0 = *reinterpret_cast<const float4*>(s);
    const float4 v1 = *reinterpret_cast<const float4*>(s + 4);
    __nv_bfloat162 h[4];
    h[0].x = __float2bfloat16(v0.x); h[0].y = __float2bfloat16(v0.y);
    h[1].x = __float2bfloat16(v0.z); h[1].y = __float2bfloat16(v0.w);
    h[2].x = __float2bfloat16(v1.x); h[2].y = __float2bfloat16(v1.y);
    h[3].x = __float2bfloat16(v1.z); h[3].y = __float2bfloat16(v1.w);
    *reinterpret_cast<uint4*>(d) = *reinterpret_cast<uint4*>(h);
}

// Grid barrier: monotonic ticket, graph-replay safe.
__device__ __forceinline__ void grid_barrier() {
    __threadfence();
    __syncthreads();
    if (threadIdx.x == 0) {
        const unsigned t = atomicAdd(&g_bar, 1u);
        const unsigned target = t - (t % NBLK) + NBLK;
        while (*(volatile unsigned*)&g_bar < target) { }
        __threadfence();
    }
    __syncthreads();
}

// ===========================================================================
// Persistent kernel:
//   Phase A: flag reset + W1/W2 convert + LN      | grid barrier |
//   Phase B: GEMM1 tile (mt, nt) -> hid, set flag[mt*8+nt]
//   Phase C: GEMM2 tile (mt, nt); chunk c waits flag[mt*8+c] (own chunk free)
// 128 CTAs x 256 threads. No barrier between B and C.
// ===========================================================================
__global__ void __launch_bounds__(NTHR, 1)
block_fused(const float* __restrict__ x,
            const float* __restrict__ bp,
            const float* __restrict__ g2,
            const float* __restrict__ b2,
            const float* __restrict__ W1,
            const float* __restrict__ bf1,
            const float* __restrict__ W2,
            const float* __restrict__ bf2,
            float* __restrict__ out)
{
    extern __shared__ char smem[];
    const int bid  = blockIdx.x;
    const int tid  = threadIdx.x;
    const int lane = tid & 31;
    const int warp = tid >> 5;
    const int mt   = bid >> 3;          // m-strip (16)
    const int nt   = bid & 7;           // n-tile  (8)
    const int m0   = mt * 64;

    // ---------------- Phase A: flag reset + convert + LN -------------------
    if (tid == 0) g_flag[bid] = 0;
    {
        // W1, W2: 262144 floats each / 128 blocks / 256 thr = 8 floats each
        const int i8 = bid * 2048 + tid * 8;
        cvt8(W1 + i8, g_W1 + i8);
        cvt8(W2 + i8, g_W2 + i8);
        // LN: 8 warps, one row each -> rows bid*8 .. bid*8+7
        const int row = bid * 8 + warp;
        const int c0  = lane * 8;
        const float* rp = x + (size_t)row * Cdim + c0;
        float v[8];
        {
            const float4 a  = *reinterpret_cast<const float4*>(rp);
            const float4 b  = *reinterpret_cast<const float4*>(rp + 4);
            const float4 pa = *reinterpret_cast<const float4*>(bp + c0);
            const float4 pb = *reinterpret_cast<const float4*>(bp + c0 + 4);
            v[0] = a.x + pa.x; v[1] = a.y + pa.y; v[2] = a.z + pa.z; v[3] = a.w + pa.w;
            v[4] = b.x + pb.x; v[5] = b.y + pb.y; v[6] = b.z + pb.z; v[7] = b.w + pb.w;
        }
        float s = 0.f, q = 0.f;
        #pragma unroll
        for (int j = 0; j < 8; j++) { s += v[j]; q += v[j] * v[j]; }
        #pragma unroll
        for (int o = 16; o > 0; o >>= 1) {
            s += __shfl_xor_sync(0xffffffffu, s, o);
            q += __shfl_xor_sync(0xffffffffu, q, o);
        }
        const float mean = s * (1.0f / Cdim);
        const float var  = q * (1.0f / Cdim) - mean * mean;
        const float inv  = rsqrtf(var + 1e-5f);
        const float4 ga = *reinterpret_cast<const float4*>(g2 + c0);
        const float4 gb = *reinterpret_cast<const float4*>(g2 + c0 + 4);
        const float4 ba = *reinterpret_cast<const float4*>(b2 + c0);
        const float4 bb = *reinterpret_cast<const float4*>(b2 + c0 + 4);
        const float gg[8]  = {ga.x, ga.y, ga.z, ga.w, gb.x, gb.y, gb.z, gb.w};
        const float bbv[8] = {ba.x, ba.y, ba.z, ba.w, bb.x, bb.y, bb.z, bb.w};
        __nv_bfloat162 o2[4];
        #pragma unroll
        for (int j = 0; j < 4; j++) {
            o2[j].x = __float2bfloat16((v[2*j]   - mean) * inv * gg[2*j]   + bbv[2*j]);
            o2[j].y = __float2bfloat16((v[2*j+1] - mean) * inv * gg[2*j+1] + bbv[2*j+1]);
        }
        *reinterpret_cast<uint4*>(&g_h2[(size_t)row * Cdim + c0]) =
            *reinterpret_cast<uint4*>(o2);
    }

    grid_barrier();

    // ---------------- Phase B: GEMM1 (64 x 128, K=256, BK=64) ---------------
    {
        constexpr int BM = 64, BN = 128, BK = 64, LDS = 72;
        __nv_bfloat16* As = reinterpret_cast<__nv_bfloat16*>(smem);
        __nv_bfloat16* Bs = As + 2 * BM * LDS;
        const int n0 = nt * 128;
        const int wm = warp >> 2;      // 2x4 warps: WM=32, WN=32
        const int wn = warp & 3;

        auto load_stage = [&](int buf, int k0) {
            __nv_bfloat16* Ab = As + buf * BM * LDS;
            __nv_bfloat16* Bb = Bs + buf * BN * LDS;
            #pragma unroll
            for (int i = tid; i < BM * BK / 8; i += NTHR) {
                const int r = i / (BK / 8), cv = i % (BK / 8);
                cp_async16(smem_u32(&Ab[r * LDS + cv * 8]),
                           &g_h2[(size_t)(m0 + r) * Cdim + k0 + cv * 8]);
            }
            #pragma unroll
            for (int i = tid; i < BN * BK / 8; i += NTHR) {
                const int r = i / (BK / 8), cv = i % (BK / 8);
                cp_async16(smem_u32(&Bs[buf * BN * LDS + r * LDS + cv * 8]),
                           &g_W1[(size_t)(n0 + r) * Cdim + k0 + cv * 8]);
            }
            (void)Bb;
            cp_commit();
        };

        float acc[2][4][4];
        #pragma unroll
        for (int i = 0; i < 2; i++)
            #pragma unroll
            for (int j = 0; j < 4; j++)
                #pragma unroll
                for (int r = 0; r < 4; r++) acc[i][j][r] = 0.f;

        load_stage(0, 0);
        for (int it = 0; it < 4; it++) {
            const int buf = it & 1;
            if (it + 1 < 4) { load_stage((it + 1) & 1, (it + 1) * BK); cp_wait<1>(); }
            else            { cp_wait<0>(); }
            __syncthreads();

            const __nv_bfloat16* Ab = As + buf * BM * LDS;
            const __nv_bfloat16* Bb = Bs + buf * BN * LDS;
            #pragma unroll
            for (int ks = 0; ks < BK; ks += 16) {
                uint32_t afrag[2][4];
                #pragma unroll
                for (int mtl = 0; mtl < 2; mtl++) {
                    const int row = wm * 32 + mtl * 16 + (lane & 15);
                    const int col = ks + (lane >> 4) * 8;
                    ldsm_x4(afrag[mtl][0], afrag[mtl][1], afrag[mtl][2], afrag[mtl][3],
                            smem_u32(&Ab[row * LDS + col]));
                }
                uint32_t bfrag[4][2];
                #pragma unroll
                for (int ntl = 0; ntl < 4; ntl++) {
                    const int row = wn * 32 + ntl * 8 + (lane & 7);
                    const int col = ks + ((lane >> 3) & 1) * 8;
                    ldsm_x2(bfrag[ntl][0], bfrag[ntl][1],
                            smem_u32(&Bb[row * LDS + col]));
                }
                #pragma unroll
                for (int mtl = 0; mtl < 2; mtl++)
                    #pragma unroll
                    for (int ntl = 0; ntl < 4; ntl++)
                        mma_bf16(acc[mtl][ntl], afrag[mtl], bfrag[ntl]);
            }
            __syncthreads();
        }

        // Epilogue: relu(acc + bf1) -> bf16 g_hid
        #pragma unroll
        for (int mtl = 0; mtl < 2; mtl++) {
            #pragma unroll
            for (int ntl = 0; ntl < 4; ntl++) {
                const int m = m0 + wm * 32 + mtl * 16 + (lane >> 2);
                const int n = n0 + wn * 32 + ntl * 8 + (lane & 3) * 2;
                const float b0 = bf1[n], b1 = bf1[n + 1];
                __nv_bfloat162 p;
                p.x = __float2bfloat16(fmaxf(acc[mtl][ntl][0] + b0, 0.f));
                p.y = __float2bfloat16(fmaxf(acc[mtl][ntl][1] + b1, 0.f));
                *reinterpret_cast<__nv_bfloat162*>(&g_hid[(size_t)m * Hdim + n]) = p;
                p.x = __float2bfloat16(fmaxf(acc[mtl][ntl][2] + b0, 0.f));
                p.y = __float2bfloat16(fmaxf(acc[mtl][ntl][3] + b1, 0.f));
                *reinterpret_cast<__nv_bfloat162*>(&g_hid[(size_t)(m + 8) * Hdim + n]) = p;
            }
        }
    }

    // Publish hid tile
    __threadfence();
    __syncthreads();
    if (tid == 0) *(volatile int*)&g_flag[bid] = 1;

    // ---------------- Phase C: GEMM2 (64 x 32, K=1024 in 8 chunks) ---------
    {
        constexpr int BM = 64, BN = 32, BK = 128, LDS = 136;
        __nv_bfloat16* As = reinterpret_cast<__nv_bfloat16*>(smem);
        __nv_bfloat16* Bs = As + 2 * BM * LDS;
        const int n0 = nt * 32;
        const int wm = warp >> 1;      // 4x2 warps: WM=16, WN=16
        const int wn = warp & 1;

        auto load_chunk = [&](int buf, int c) {
            __nv_bfloat16* Ab = As + buf * BM * LDS;
            __nv_bfloat16* Bb = Bs + buf * BN * LDS;
            #pragma unroll
            for (int i = tid; i < BM * BK / 8; i += NTHR) {
                const int r = i / (BK / 8), cv = i % (BK / 8);
                cp_async16(smem_u32(&Ab[r * LDS + cv * 8]),
                           &g_hid[(size_t)(m0 + r) * Hdim + c * BK + cv * 8]);
            }
            #pragma unroll
            for (int i = tid; i < BN * BK / 8; i += NTHR) {
                const int r = i / (BK / 8), cv = i % (BK / 8);
                cp_async16(smem_u32(&Bb[r * LDS + cv * 8]),
                           &g_W2[(size_t)(n0 + r) * Hdim + c * BK + cv * 8]);
            }
            cp_commit();
        };
        auto wait_chunk = [&](int c) {
            if (tid == 0) {
                while (*(volatile int*)&g_flag[mt * 8 + c] == 0) { }
            }
            __syncthreads();
        };

        float acc[2][4] = {};

        // Chunk order: own chunk first (flag set by self), then round-robin.
        load_chunk(0, nt);   // no wait needed

        for (int i = 0; i < 8; i++) {
            const int buf = i & 1;
            if (i + 1 < 8) {
                const int cn = (nt + i + 1) & 7;
                wait_chunk(cn);
                load_chunk((i + 1) & 1, cn);
                cp_wait<1>();
            } else {
                cp_wait<0>();
            }
            __syncthreads();

            const __nv_bfloat16* Ab = As + buf * BM * LDS;
            const __nv_bfloat16* Bb = Bs + buf * BN * LDS;
            #pragma unroll
            for (int ks = 0; ks < BK; ks += 16) {
                uint32_t afrag[4];
                {
                    const int row = wm * 16 + (lane & 15);
                    const int col = ks + (lane >> 4) * 8;
                    ldsm_x4(afrag[0], afrag[1], afrag[2], afrag[3],
                            smem_u32(&Ab[row * LDS + col]));
                }
                uint32_t bfrag[2][2];
                #pragma unroll
                for (int ntl = 0; ntl < 2; ntl++) {
                    const int row = wn * 16 + ntl * 8 + (lane & 7);
                    const int col = ks + ((lane >> 3) & 1) * 8;
                    ldsm_x2(bfrag[ntl][0], bfrag[ntl][1],
                            smem_u32(&Bb[row * LDS + col]));
                }
                #pragma unroll
                for (int ntl = 0; ntl < 2; ntl++)
                    mma_bf16(acc[ntl], afrag, bfrag[ntl]);
            }
            __syncthreads();
        }

        // Epilogue: acc + x + bp + bf2 -> fp32 out
        #pragma unroll
        for (int ntl = 0; ntl < 2; ntl++) {
            const int m = m0 + wm * 16 + (lane >> 2);
            const int n = n0 + wn * 16 + ntl * 8 + (lane & 3) * 2;
            const float b0 = bp[n] + bf2[n];
            const float b1 = bp[n + 1] + bf2[n + 1];
            const float2 r0 = *reinterpret_cast<const float2*>(&x[(size_t)m * Cdim + n]);
            const float2 r1 = *reinterpret_cast<const float2*>(&x[(size_t)(m + 8) * Cdim + n]);
            float2 p;
            p.x = acc[ntl][0] + r0.x + b0; p.y = acc[ntl][1] + r0.y + b1;
            *reinterpret_cast<float2*>(&out[(size_t)m * Cdim + n]) = p;
            p.x = acc[ntl][2] + r1.x + b0; p.y = acc[ntl][3] + r1.y + b1;
            *reinterpret_cast<float2*>(&out[(size_t)(m + 8) * Cdim + n]) = p;
        }
    }
}

// ---------------------------------------------------------------------------
// Attention branch is exactly 0 (transform *= 0.0)  =>  sa == bp.
//   y = (x + bp) + relu(LN(x+bp)@W1^T + bf1) @ W2^T + bf2
// Inputs: 0:x 1:Wt 2:Wp 3:bp 4:g1 5:b1 6:g2 7:b2 8:W1 9:bf1 10:W2 11:bf2
// ---------------------------------------------------------------------------
extern "C" void kernel_launch(void* const* d_in, const int* in_sizes, int n_in,
                              void* d_out, int out_size)
{
    const float* x   = (const float*)d_in[0];
    const float* bp  = (const float*)d_in[3];
    const float* g2  = (const float*)d_in[6];
    const float* b2  = (const float*)d_in[7];
    const float* W1  = (const float*)d_in[8];
    const float* bf1 = (const float*)d_in[9];
    const float* W2  = (const float*)d_in[10];
    const float* bf2 = (const float*)d_in[11];
    float* out = (float*)d_out;

    // smem = max(phase B, phase C):
    //   B: 2*(64*72 + 128*72)*2 = 55296 ;  C: 2*(64*136 + 32*136)*2 = 52224
    constexpr int SMEM = 2 * (64 * 72 + 128 * 72) * 2;
    cudaFuncSetAttribute(block_fused,
                         cudaFuncAttributeMaxDynamicSharedMemorySize, SMEM);

    block_fused<<<NBLK, NTHR, SMEM>>>(x, bp, g2, b2, W1, bf1, W2, bf2, out);
}